// round 7
// baseline (speedup 1.0000x reference)
#include <cuda_runtime.h>
#include <math.h>

#define BB 4
#define NN 96
#define CC 64

typedef unsigned long long u64;

// ---------------- packed f32x2 helpers ----------------
__device__ __forceinline__ void unpack2(u64 v, float &lo, float &hi) {
    asm("mov.b64 {%0, %1}, %2;" : "=f"(lo), "=f"(hi) : "l"(v));
}
__device__ __forceinline__ u64 pack2(float lo, float hi) {
    u64 d; asm("mov.b64 %0, {%1, %2};" : "=l"(d) : "f"(lo), "f"(hi)); return d;
}
__device__ __forceinline__ void fma2(u64 &acc, u64 a, u64 b) {
    asm("fma.rn.f32x2 %0, %1, %2, %0;" : "+l"(acc) : "l"(a), "l"(b));
}

// ---------------- device scratch (static: no runtime allocation allowed) ----------------
__device__ float g_P[(size_t)BB * NN * CC * 16 * 16 * 2];   // 50.3 MB pair products
__device__ float g_cat[16121856];                           // 64.5 MB cat buffers (all l)
__device__ float g_CG[4 * 4 * 4 * 7 * 7 * 7];               // dense CG table

// ---------------- constant tables ----------------
__constant__ int PBASE[4]    = {0, 1, 4, 9};
__constant__ int L1_OF_P[16] = {0, 1,1,1, 2,2,2,2,2, 3,3,3,3,3,3,3};
__constant__ int PAIR_OFF[5] = {0, 4, 13, 24, 34};
__constant__ int PAIR_L1[34] = {
    0,1,2,3,
    0,1,1,1,2,2,2,3,3,
    0,1,1,1,2,2,2,2,3,3,3,
    0,1,1,2,2,2,3,3,3,3};
__constant__ int PAIR_L2[34] = {
    0,1,2,3,
    1,0,1,2,1,2,3,2,3,
    2,1,2,3,0,1,2,3,1,2,3,
    3,2,3,1,2,3,0,1,2,3};
__constant__ int NPAIR[4] = {4, 9, 11, 10};
__constant__ int TW[4]    = {576, 1216, 1472, 1344};
__constant__ size_t CAT_OFF[4] = {0, 442368, 3244032, 8896512};
__constant__ size_t OUT_OFF[4] = {0, 49152, 196608, 442368};
__constant__ int SLOT_CUM[4] = {0, 9, 66, 181};

// ---------------- init: Clebsch-Gordan table ----------------
__device__ double dfact(int n) { double r = 1.0; for (int i = 2; i <= n; i++) r *= (double)i; return r; }

__global__ void init_cg() {
    int idx = blockIdx.x * blockDim.x + threadIdx.x;
    const int total = 4 * 4 * 4 * 7 * 7 * 7;
    for (int t = idx; t < total; t += gridDim.x * blockDim.x) {
        int m  = t % 7; int r = t / 7;
        int j2 = r % 7; r /= 7;
        int i1 = r % 7; r /= 7;
        int l  = r % 4; r /= 4;
        int l2 = r % 4; r /= 4;
        int l1 = r;
        float v = 0.f;
        if (i1 <= 2 * l1 && j2 <= 2 * l2 && m <= 2 * l &&
            l >= abs(l1 - l2) && l <= l1 + l2) {
            int m1 = i1 - l1, m2 = j2 - l2, mm = m - l;
            if (mm == m1 + m2) {
                double pre = sqrt((2.0 * l + 1.0) * dfact(l + l1 - l2) * dfact(l - l1 + l2) *
                                  dfact(l1 + l2 - l) / dfact(l1 + l2 + l + 1));
                pre *= sqrt(dfact(l + mm) * dfact(l - mm) * dfact(l1 - m1) * dfact(l1 + m1) *
                            dfact(l2 - m2) * dfact(l2 + m2));
                int kmin = max(0, max(l2 - l - m1, l1 - l + m2));
                int kmax = min(l1 + l2 - l, min(l1 - m1, l2 + m2));
                double s = 0.0;
                for (int k = kmin; k <= kmax; k++) {
                    double term = 1.0 / (dfact(k) * dfact(l1 + l2 - l - k) * dfact(l1 - m1 - k) *
                                         dfact(l2 + m2 - k) * dfact(l - l2 + m1 + k) * dfact(l - l1 - m2 + k));
                    s += (k & 1) ? -term : term;
                }
                v = (float)(pre * s);
            }
        }
        g_CG[t] = v;
    }
}

// ---------------- k1: P[b,i,c,p,q] = sum_j E[b,i,j,c,p] * A[b,j,c,q] (complex, FFMA2) ----------------
// grid (4 c-chunks of 16, N, B) = 1536 CTAs, 256 threads.
// Thread owns (c_loc, p); accumulators are packed over q-pairs (16 u64 = 16 complex q).
#define JT 8
__global__ void __launch_bounds__(256) k1_pair(
    const float* __restrict__ e0, const float* __restrict__ e1,
    const float* __restrict__ e2, const float* __restrict__ e3,
    const float* __restrict__ a0, const float* __restrict__ a1,
    const float* __restrict__ a2, const float* __restrict__ a3)
{
    const int cchunk = blockIdx.x;
    const int i = blockIdx.y, bb = blockIdx.z;
    const int c0 = cchunk * 16;
    const int bi = bb * NN + i;
    const int tid = threadIdx.x;

    __shared__ __align__(16) float Es[JT * 16 * 32];   // [jj][c][p][{re,im}]
    __shared__ __align__(16) float Ar[JT * 16 * 16];   // [jj][c][q] re plane (row = 64B aligned)
    __shared__ __align__(16) float Ai[JT * 16 * 16];   // [jj][c][q] im plane

    // loader mapping: contiguous (c,m) per l so LDGs coalesce within each l-tensor
    int ll, tg;
    if (tid < 16)       { ll = 0; tg = tid; }
    else if (tid < 64)  { ll = 1; tg = tid - 16; }
    else if (tid < 144) { ll = 2; tg = tid - 64; }
    else                { ll = 3; tg = tid - 144; }
    const int dimL = 2 * ll + 1;
    const int lc = tg / dimL, lm = tg - lc * dimL;
    const int lp = PBASE[ll] + lm;
    const float* esrc = (ll == 0) ? e0 : (ll == 1) ? e1 : (ll == 2) ? e2 : e3;
    const float* asrc = (ll == 0) ? a0 : (ll == 1) ? a1 : (ll == 2) ? a2 : a3;
    const size_t estride = (size_t)CC * dimL * 2;
    const size_t ebase = ((size_t)bi * NN * CC + (c0 + lc)) * dimL * 2 + lm * 2;
    const size_t abase = ((size_t)bb * NN * CC + (c0 + lc)) * dimL * 2 + lm * 2;

    // compute mapping: warp covers 2 c's x 16 p's
    const int w = tid >> 5, lane = tid & 31;
    const int ch = lane >> 4, p = lane & 15;
    const int cloc = w * 2 + ch;

    u64 aRe[8], aIm[8];   // aRe[t] holds re parts of q=2t, 2t+1 (packed)
#pragma unroll
    for (int t = 0; t < 8; t++) { aRe[t] = 0ull; aIm[t] = 0ull; }

    for (int j0 = 0; j0 < NN; j0 += JT) {
#pragma unroll
        for (int jj = 0; jj < JT; jj++) {
            float2 ev = *(const float2*)(esrc + ebase + (size_t)(j0 + jj) * estride);
            float2 av = *(const float2*)(asrc + abase + (size_t)(j0 + jj) * estride);
            *(float2*)&Es[(jj * 16 + lc) * 32 + lp * 2] = ev;
            Ar[(jj * 16 + lc) * 16 + lp] = av.x;
            Ai[(jj * 16 + lc) * 16 + lp] = av.y;
        }
        __syncthreads();
#pragma unroll
        for (int jj = 0; jj < JT; jj++) {
            float2 e = *(const float2*)&Es[(jj * 16 + cloc) * 32 + p * 2];
            float ny = -e.y;
            u64 err = pack2(e.x, e.x);
            u64 eii = pack2(e.y, e.y);
            u64 nei = pack2(ny, ny);
            const ulonglong2* arp = (const ulonglong2*)&Ar[(jj * 16 + cloc) * 16]; // 64B aligned
            const ulonglong2* aip = (const ulonglong2*)&Ai[(jj * 16 + cloc) * 16];
#pragma unroll
            for (int t = 0; t < 4; t++) {
                ulonglong2 ar2 = arp[t];   // q = 4t..4t+3 re
                ulonglong2 ai2 = aip[t];   // q = 4t..4t+3 im
                fma2(aRe[2 * t],     err, ar2.x); fma2(aRe[2 * t],     nei, ai2.x);
                fma2(aIm[2 * t],     err, ai2.x); fma2(aIm[2 * t],     eii, ar2.x);
                fma2(aRe[2 * t + 1], err, ar2.y); fma2(aRe[2 * t + 1], nei, ai2.y);
                fma2(aIm[2 * t + 1], err, ai2.y); fma2(aIm[2 * t + 1], eii, ar2.y);
            }
        }
        __syncthreads();
    }
    // write P[bi, c, p, q, {re,im}] — 32 contiguous floats per thread
    float4* pout = (float4*)(g_P + (((size_t)bi * CC + c0 + cloc) * 256 + p * 16) * 2);
#pragma unroll
    for (int t = 0; t < 8; t++) {
        float r0, r1, i0, i1;
        unpack2(aRe[t], r0, r1);   // q=2t, 2t+1 re
        unpack2(aIm[t], i0, i1);
        pout[t] = make_float4(r0, i0, r1, i1);
    }
}

// ---------------- k2: CG contraction of P, identity, self tensor-product -> cat ----------------
__global__ void __launch_bounds__(256) k2_cg(
    const float* __restrict__ a0, const float* __restrict__ a1,
    const float* __restrict__ a2, const float* __restrict__ a3)
{
    const int cchunk = blockIdx.x;
    const int i = blockIdx.y, b = blockIdx.z;
    const int c0 = cchunk * 16;
    const int bi = b * NN + i;
    const int tid = threadIdx.x;

    __shared__ float Ps[16 * 516];
    __shared__ float Asm[16 * 34];

    const float4* psrc = (const float4*)(g_P + ((size_t)bi * CC + c0) * 512);
    for (int t = tid; t < 16 * 128; t += 256) {
        int cl = t >> 7, x4 = t & 127;
        float4 v = psrc[cl * 128 + x4];
        *(float4*)&Ps[cl * 516 + x4 * 4] = v;
    }
    for (int t = tid; t < 16 * 32; t += 256) {
        int cl = t >> 5, x = t & 31;
        int pg = x >> 1, ri = x & 1;
        int l2 = L1_OF_P[pg], mm = pg - PBASE[l2];
        const float* ap = (l2 == 0) ? a0 : (l2 == 1) ? a1 : (l2 == 2) ? a2 : a3;
        Asm[cl * 34 + x] = ap[(((size_t)bi * CC + c0 + cl) * (2 * l2 + 1) + mm) * 2 + ri];
    }
    __syncthreads();

    for (int it = tid; it < 328 * 16; it += 256) {
        int slot = it >> 4, cl = it & 15;
        int l = (slot < 9) ? 0 : (slot < 66) ? 1 : (slot < 181) ? 2 : 3;
        int sp = slot - SLOT_CUM[l];
        int dim = 2 * l + 1;
        int blk = sp / dim, m = sp % dim;
        int np = NPAIR[l];
        float zr = 0.f, zi = 0.f;
        if (blk == np) {
            int pg = PBASE[l] + m;
            zr = Asm[cl * 34 + pg * 2];
            zi = Asm[cl * 34 + pg * 2 + 1];
        } else {
            int k = (blk < np) ? blk : blk - np - 1;
            int l1 = PAIR_L1[PAIR_OFF[l] + k], l2 = PAIR_L2[PAIR_OFF[l] + k];
            const float* cg = &g_CG[((l1 * 4 + l2) * 4 + l) * 343];
            if (blk < np) {
                const float* pc = &Ps[cl * 516];
                for (int i1 = 0; i1 <= 2 * l1; i1++) {
                    int j2 = m - l - i1 + l1 + l2;
                    if (j2 >= 0 && j2 <= 2 * l2) {
                        float coef = cg[(i1 * 7 + j2) * 7 + m];
                        int pp = PBASE[l1] + i1, qq = PBASE[l2] + j2;
                        zr = fmaf(coef, pc[(pp * 16 + qq) * 2], zr);
                        zi = fmaf(coef, pc[(pp * 16 + qq) * 2 + 1], zi);
                    }
                }
            } else {
                const float* am = &Asm[cl * 34];
                for (int i1 = 0; i1 <= 2 * l1; i1++) {
                    int j2 = m - l - i1 + l1 + l2;
                    if (j2 >= 0 && j2 <= 2 * l2) {
                        float coef = cg[(i1 * 7 + j2) * 7 + m];
                        int pp = PBASE[l1] + i1, qq = PBASE[l2] + j2;
                        float x1r = am[pp * 2], x1i = am[pp * 2 + 1];
                        float x2r = am[qq * 2], x2i = am[qq * 2 + 1];
                        zr = fmaf(coef, x1r * x2r - x1i * x2i, zr);
                        zi = fmaf(coef, x1r * x2i + x1i * x2r, zi);
                    }
                }
            }
        }
        size_t addr = CAT_OFF[l] + ((size_t)(bi * dim + m) * TW[l] + blk * CC + c0 + cl) * 2;
        g_cat[addr]     = zr;
        g_cat[addr + 1] = zi;
    }
}

// ---------------- k3: fused complex GEMM (FFMA2), 16-row x 64-d tiles, 384 CTAs, 128 threads ----------------
// Thread owns 4 rows x 2 d; accumulators packed over d-pairs.
// cat is staged into duplicated planes so no register packs are needed in the inner loop.
__global__ void __launch_bounds__(128) k3_gemm(
    const float* __restrict__ w0, const float* __restrict__ w1,
    const float* __restrict__ w2, const float* __restrict__ w3,
    float* __restrict__ out)
{
    const int blk = blockIdx.x;
    int l, rt0;
    if      (blk < 24)  { l = 0; rt0 = blk; }
    else if (blk < 96)  { l = 1; rt0 = blk - 24; }
    else if (blk < 216) { l = 2; rt0 = blk - 96; }
    else                { l = 3; rt0 = blk - 216; }
    const int T = TW[l], dim = 2 * l + 1;
    const int row0 = rt0 * 16;
    const float* wsrc = (l == 0) ? w0 : (l == 1) ? w1 : (l == 2) ? w2 : w3;
    const float* catl = g_cat + CAT_OFF[l];

    // c planes: [k][row] as duplicated pairs; stride 34 floats (even -> 8B-aligned u64 reads)
    __shared__ __align__(16) float csrr[32 * 34];   // (cr, cr)
    __shared__ __align__(16) float csii[32 * 34];   // (ci, ci)
    __shared__ __align__(16) float csni[32 * 34];   // (-ci, -ci)
    // w planes: [k][d]; stride 66 floats (even -> 8B-aligned u64 reads over d-pairs)
    __shared__ __align__(16) float wsr[32 * 66];
    __shared__ __align__(16) float wsi[32 * 66];

    const int tid = threadIdx.x;
    const int w = tid >> 5, L = tid & 31;    // warp w: rows w*4..w*4+3 ; lane L: d = 2L, 2L+1

    u64 accRe[4] = {0ull, 0ull, 0ull, 0ull};
    u64 accIm[4] = {0ull, 0ull, 0ull, 0ull};

    const int nK = T >> 5;
    for (int kt = 0; kt < nK; kt++) {
        const int T0 = kt * 32;
        // cat loader: 512 (k,row) entries, 4 per thread
#pragma unroll
        for (int t = 0; t < 4; t++) {
            int idx = tid + t * 128;
            int r = idx >> 5, k = idx & 31;
            float2 v = *(const float2*)(catl + ((size_t)(row0 + r) * T + T0 + k) * 2);
            *(float2*)&csrr[k * 34 + r * 2] = make_float2(v.x, v.x);
            *(float2*)&csii[k * 34 + r * 2] = make_float2(v.y, v.y);
            *(float2*)&csni[k * 34 + r * 2] = make_float2(-v.y, -v.y);
        }
        // w loader: 2048 (k,d) entries, 16 per thread
#pragma unroll
        for (int t = 0; t < 16; t++) {
            int idx = tid + t * 128;
            int d = idx >> 5, k = idx & 31;
            float2 v = *(const float2*)(wsrc + ((size_t)d * T + T0 + k) * 2);
            wsr[k * 66 + d] = v.x;
            wsi[k * 66 + d] = v.y;
        }
        __syncthreads();
#pragma unroll 4
        for (int k = 0; k < 32; k++) {
            u64 wr = *(const u64*)&wsr[k * 66 + 2 * L];
            u64 wi = *(const u64*)&wsi[k * 66 + 2 * L];
#pragma unroll
            for (int r = 0; r < 4; r++) {
                int row = w * 4 + r;
                u64 crr = *(const u64*)&csrr[k * 34 + row * 2];  // warp-uniform broadcast
                u64 cii = *(const u64*)&csii[k * 34 + row * 2];
                u64 cni = *(const u64*)&csni[k * 34 + row * 2];
                fma2(accRe[r], wr, crr);
                fma2(accRe[r], wi, cni);
                fma2(accIm[r], wr, cii);
                fma2(accIm[r], wi, crr);
            }
        }
        __syncthreads();
    }

    float* ob = out + OUT_OFF[l];
#pragma unroll
    for (int r = 0; r < 4; r++) {
        int grow = row0 + w * 4 + r;
        int bi = grow / dim, m = grow - bi * dim;
        float r0, r1, i0, i1;
        unpack2(accRe[r], r0, r1);   // d=2L, 2L+1 re
        unpack2(accIm[r], i0, i1);
        size_t a0 = ((size_t)(bi * CC + 2 * L) * dim + m) * 2;
        *(float2*)&ob[a0]           = make_float2(r0, i0);
        *(float2*)&ob[a0 + dim * 2] = make_float2(r1, i1);
    }
}

// ---------------- launch ----------------
extern "C" void kernel_launch(void* const* d_in, const int* in_sizes, int n_in,
                              void* d_out, int out_size)
{
    const float *atomp[4] = {0, 0, 0, 0}, *edgep[4] = {0, 0, 0, 0}, *wp[4] = {0, 0, 0, 0};
    for (int idx = 0; idx < n_in; idx++) {
        int s = in_sizes[idx];
        const float* ptr = (const float*)d_in[idx];
        switch (s) {
            case 49152:    atomp[0] = ptr; break;
            case 147456:   atomp[1] = ptr; break;
            case 245760:   atomp[2] = ptr; break;
            case 344064:   atomp[3] = ptr; break;
            case 4718592:  edgep[0] = ptr; break;
            case 14155776: edgep[1] = ptr; break;
            case 23592960: edgep[2] = ptr; break;
            case 33030144: edgep[3] = ptr; break;
            case 73728:    wp[0] = ptr; break;
            case 155648:   wp[1] = ptr; break;
            case 188416:   wp[2] = ptr; break;
            case 172032:   wp[3] = ptr; break;
            default: break; // mask (384) unused
        }
    }
    init_cg<<<32, 256>>>();
    dim3 g1(4, NN, BB);
    k1_pair<<<g1, 256>>>(edgep[0], edgep[1], edgep[2], edgep[3],
                         atomp[0], atomp[1], atomp[2], atomp[3]);
    dim3 g2(4, NN, BB);
    k2_cg<<<g2, 256>>>(atomp[0], atomp[1], atomp[2], atomp[3]);
    k3_gemm<<<384, 128>>>(wp[0], wp[1], wp[2], wp[3], (float*)d_out);
}